// round 13
// baseline (speedup 1.0000x reference)
#include <cuda_runtime.h>
#include <cuda_bf16.h>
#include <cstdint>

// TransINT scoring, single-pass quadratic form, 256-BIT LOADS (sm_103 LDG.256):
// one ld.global.nc.v8.b32 per 1KB row (lane L owns bytes [32L,32L+32)), so a
// sample needs 7 memory requests instead of 14. The chip is capped by
// outstanding-request concurrency (~55/SM), so halving requests doubles
// effective bytes-in-flight.
//   re = heads[rel2head[r]] * rel2mult[r]        (r = pos_r; neg_r unused)
//   s_pos = ent[ph] + re - ent[pt];  s_neg = ent[nh] + re - ent[nt]
//   A = bases[r] (2 x 256); c = ATA^{-1} (A.s)
//   exact-solution identity: ||s - A^T c||^2 = s.s - c.(A.s)
// out[0:B) = pos, out[B:2B) = neg (float32)

#define D 256
#define WARPS_PER_BLOCK 8

struct F8 { float v[8]; };

__device__ __forceinline__ F8 ldg256(const float* p) {
    unsigned a0, a1, a2, a3, a4, a5, a6, a7;
    asm volatile("ld.global.nc.v8.b32 {%0,%1,%2,%3,%4,%5,%6,%7}, [%8];"
                 : "=r"(a0), "=r"(a1), "=r"(a2), "=r"(a3),
                   "=r"(a4), "=r"(a5), "=r"(a6), "=r"(a7)
                 : "l"(p));
    F8 o;
    o.v[0] = __uint_as_float(a0); o.v[1] = __uint_as_float(a1);
    o.v[2] = __uint_as_float(a2); o.v[3] = __uint_as_float(a3);
    o.v[4] = __uint_as_float(a4); o.v[5] = __uint_as_float(a5);
    o.v[6] = __uint_as_float(a6); o.v[7] = __uint_as_float(a7);
    return o;
}

__global__ __launch_bounds__(WARPS_PER_BLOCK * 32, 4)
void transint_kernel(const int* __restrict__ pos_h,
                     const int* __restrict__ pos_t,
                     const int* __restrict__ pos_r,
                     const int* __restrict__ neg_h,
                     const int* __restrict__ neg_t,
                     const float* __restrict__ ent_emb,   // E x D
                     const float* __restrict__ heads,     // K x D
                     const float* __restrict__ bases,     // R x 2 x D
                     const int* __restrict__ rel2head,
                     const float* __restrict__ rel2mult,
                     float* __restrict__ out,
                     int B)
{
    const int warp = blockIdx.x * WARPS_PER_BLOCK + (threadIdx.x >> 5);
    if (warp >= B) return;
    const int lane = threadIdx.x & 31;

    // Per-sample indices (uniform across warp; broadcast loads)
    const int ph = pos_h[warp];
    const int pt = pos_t[warp];
    const int r  = pos_r[warp];
    const int nh = neg_h[warp];
    const int nt = neg_t[warp];
    const int hd = rel2head[r];
    const float mult = rel2mult[r];

    // Lane L owns floats [8L, 8L+8) of each 256-float row: one LDG.256 per row
    const int off = lane * 8;

    // 7 independent 256-bit loads issued up-front
    const F8 hp = ldg256(ent_emb + (size_t)ph * D + off);
    const F8 tp = ldg256(ent_emb + (size_t)pt * D + off);
    const F8 hn = ldg256(ent_emb + (size_t)nh * D + off);
    const F8 tn = ldg256(ent_emb + (size_t)nt * D + off);
    const F8 hh = ldg256(heads   + (size_t)hd * D + off);
    const F8 a0 = ldg256(bases   + (size_t)r * 2 * D + off);
    const F8 a1 = ldg256(bases   + (size_t)r * 2 * D + D + off);

    // 9 streamed accumulators; single pass over the data
    float aa = 0.f, ab = 0.f, dd = 0.f;
    float as0p = 0.f, as1p = 0.f, ssp = 0.f;
    float as0n = 0.f, as1n = 0.f, ssn = 0.f;

    #pragma unroll
    for (int i = 0; i < 8; i++) {
        const float re = hh.v[i] * mult;
        const float sv = hp.v[i] + re - tp.v[i];
        const float nv = hn.v[i] + re - tn.v[i];
        const float A0 = a0.v[i], A1 = a1.v[i];
        aa   = fmaf(A0, A0, aa);
        ab   = fmaf(A0, A1, ab);
        dd   = fmaf(A1, A1, dd);
        as0p = fmaf(A0, sv, as0p);
        as1p = fmaf(A1, sv, as1p);
        ssp  = fmaf(sv, sv, ssp);
        as0n = fmaf(A0, nv, as0n);
        as1n = fmaf(A1, nv, as1n);
        ssn  = fmaf(nv, nv, ssn);
    }

    // Fused butterfly allreduce of 9 scalars
    #pragma unroll
    for (int m = 16; m > 0; m >>= 1) {
        aa   += __shfl_xor_sync(0xffffffffu, aa,   m);
        ab   += __shfl_xor_sync(0xffffffffu, ab,   m);
        dd   += __shfl_xor_sync(0xffffffffu, dd,   m);
        as0p += __shfl_xor_sync(0xffffffffu, as0p, m);
        as1p += __shfl_xor_sync(0xffffffffu, as1p, m);
        ssp  += __shfl_xor_sync(0xffffffffu, ssp,  m);
        as0n += __shfl_xor_sync(0xffffffffu, as0n, m);
        as1n += __shfl_xor_sync(0xffffffffu, as1n, m);
        ssn  += __shfl_xor_sync(0xffffffffu, ssn,  m);
    }

    if (lane == 0) {
        const float det = aa * dd - ab * ab;
        float scp, scn;
        if (det != 0.0f) {
            // exact normal-equation solve -> ||proj||^2 = ss - c . As
            const float inv_det = 1.0f / det;
            const float c0p = ( dd * as0p - ab * as1p) * inv_det;
            const float c1p = (-ab * as0p + aa * as1p) * inv_det;
            const float c0n = ( dd * as0n - ab * as1n) * inv_det;
            const float c1n = (-ab * as0n + aa * as1n) * inv_det;
            scp = ssp - c0p * as0p - c1p * as1p;
            scn = ssn - c0n * as0n - c1n * as1n;
        } else {
            // fallback c = As / aa is NOT the exact solution -> full quadratic
            const float inv_a = 1.0f / aa;
            const float c0p = as0p * inv_a, c1p = as1p * inv_a;
            const float c0n = as0n * inv_a, c1n = as1n * inv_a;
            scp = ssp - 2.0f * (c0p * as0p + c1p * as1p)
                + c0p * c0p * aa + 2.0f * c0p * c1p * ab + c1p * c1p * dd;
            scn = ssn - 2.0f * (c0n * as0n + c1n * as1n)
                + c0n * c0n * aa + 2.0f * c0n * c1n * ab + c1n * c1n * dd;
        }
        out[warp]     = scp;
        out[B + warp] = scn;
    }
}

extern "C" void kernel_launch(void* const* d_in, const int* in_sizes, int n_in,
                              void* d_out, int out_size) {
    const int*   pos_h    = (const int*)  d_in[0];
    const int*   pos_t    = (const int*)  d_in[1];
    const int*   pos_r    = (const int*)  d_in[2];
    const int*   neg_h    = (const int*)  d_in[3];
    const int*   neg_t    = (const int*)  d_in[4];
    // d_in[5] = neg_r (unused by the reference)
    const float* ent_emb  = (const float*)d_in[6];
    const float* heads    = (const float*)d_in[7];
    const float* bases    = (const float*)d_in[8];
    const int*   rel2head = (const int*)  d_in[9];
    const float* rel2mult = (const float*)d_in[10];
    float* out = (float*)d_out;

    const int B = in_sizes[0];
    const int blocks = (B + WARPS_PER_BLOCK - 1) / WARPS_PER_BLOCK;
    transint_kernel<<<blocks, WARPS_PER_BLOCK * 32>>>(
        pos_h, pos_t, pos_r, neg_h, neg_t,
        ent_emb, heads, bases, rel2head, rel2mult, out, B);
}

// round 15
// speedup vs baseline: 1.3245x; 1.3245x over previous
#include <cuda_runtime.h>
#include <cuda_bf16.h>
#include <cstdint>

// TransINT scoring, single-pass quadratic form, cp.async (LDGSTS) staging:
// all gathered row data flows gmem->smem via cp.async.cg (no destination
// registers, no per-warp outstanding-load cap), then each lane reads back
// ONLY the 16B chunks it copied (no cross-lane smem reads -> no syncs).
//   re = heads[rel2head[r]] * rel2mult[r]        (r = pos_r; neg_r unused)
//   s_pos = ent[ph] + re - ent[pt];  s_neg = ent[nh] + re - ent[nt]
//   A = bases[r] (2 x 256); c = ATA^{-1} (A.s)
//   exact-solution identity: ||s - A^T c||^2 = s.s - c.(A.s)
// out[0:B) = pos, out[B:2B) = neg (float32)

#define D 256
#define WARPS_PER_BLOCK 4          // 128 threads; 28KB smem -> 8 blocks/SM
#define ROW_BYTES 1024             // 256 floats
#define WARP_SMEM (7 * ROW_BYTES)  // 7 rows per sample

__device__ __forceinline__ uint32_t smem_u32(const void* p) {
    return (uint32_t)__cvta_generic_to_shared(p);
}
__device__ __forceinline__ void cp_async16(uint32_t dst, const void* src) {
    asm volatile("cp.async.cg.shared.global [%0], [%1], 16;"
                 :: "r"(dst), "l"(src));
}

__global__ __launch_bounds__(WARPS_PER_BLOCK * 32, 8)
void transint_kernel(const int* __restrict__ pos_h,
                     const int* __restrict__ pos_t,
                     const int* __restrict__ pos_r,
                     const int* __restrict__ neg_h,
                     const int* __restrict__ neg_t,
                     const float* __restrict__ ent_emb,   // E x D
                     const float* __restrict__ heads,     // K x D
                     const float* __restrict__ bases,     // R x 2 x D
                     const int* __restrict__ rel2head,
                     const float* __restrict__ rel2mult,
                     float* __restrict__ out,
                     int B)
{
    __shared__ __align__(16) char buf[WARPS_PER_BLOCK * WARP_SMEM];

    const int warp = threadIdx.x >> 5;
    const int lane = threadIdx.x & 31;
    const int s = blockIdx.x * WARPS_PER_BLOCK + warp;
    if (s >= B) return;

    // Per-sample indices (uniform across warp; broadcast loads)
    const int ph = pos_h[s];
    const int pt = pos_t[s];
    const int r  = pos_r[s];
    const int nh = neg_h[s];
    const int nt = neg_t[s];
    const int hd = rel2head[r];
    const float mult = rel2mult[r];

    const float* rows[7];
    rows[0] = ent_emb + (size_t)ph * D;
    rows[1] = ent_emb + (size_t)pt * D;
    rows[2] = ent_emb + (size_t)nh * D;
    rows[3] = ent_emb + (size_t)nt * D;
    rows[4] = heads   + (size_t)hd * D;
    rows[5] = bases   + (size_t)r * 2 * D;
    rows[6] = bases   + (size_t)r * 2 * D + D;

    // Stage all 7 rows (14 x 512B fragments) via cp.async: lane L copies the
    // float4s at indices L and L+32 of each row. 14 outstanding copies/lane,
    // zero destination registers.
    char* wbase = buf + warp * WARP_SMEM;
    const uint32_t sb = smem_u32(wbase);
    #pragma unroll
    for (int k = 0; k < 7; k++) {
        cp_async16(sb + k * ROW_BYTES + lane * 16,       rows[k] + lane * 4);
        cp_async16(sb + k * ROW_BYTES + 512 + lane * 16, rows[k] + 128 + lane * 4);
    }
    asm volatile("cp.async.commit_group;");
    asm volatile("cp.async.wait_group 0;" ::: "memory");

    // Each lane reads back exactly the bytes it copied (same thread: ordered)
    const float4* w4 = (const float4*)wbase;
    // float4 index within warp smem: row k fragment f -> k*64 + f*32 + lane
    float4 hp0 = w4[0*64 + lane],      hp1 = w4[0*64 + 32 + lane];
    float4 tp0 = w4[1*64 + lane],      tp1 = w4[1*64 + 32 + lane];
    float4 hn0 = w4[2*64 + lane],      hn1 = w4[2*64 + 32 + lane];
    float4 tn0 = w4[3*64 + lane],      tn1 = w4[3*64 + 32 + lane];
    float4 re0 = w4[4*64 + lane],      re1 = w4[4*64 + 32 + lane];
    float4 a00 = w4[5*64 + lane],      a01 = w4[5*64 + 32 + lane];
    float4 a10 = w4[6*64 + lane],      a11 = w4[6*64 + 32 + lane];

    // 9 streamed accumulators; single pass over the data
    float aa = 0.f, ab = 0.f, dd = 0.f;
    float as0p = 0.f, as1p = 0.f, ssp = 0.f;
    float as0n = 0.f, as1n = 0.f, ssn = 0.f;

    {
        const float* hpp = (const float*)&hp0; const float* hpq = (const float*)&hp1;
        const float* tpp = (const float*)&tp0; const float* tpq = (const float*)&tp1;
        const float* hnp = (const float*)&hn0; const float* hnq = (const float*)&hn1;
        const float* tnp = (const float*)&tn0; const float* tnq = (const float*)&tn1;
        const float* rep = (const float*)&re0; const float* req = (const float*)&re1;
        const float* a0p = (const float*)&a00; const float* a0q = (const float*)&a01;
        const float* a1p = (const float*)&a10; const float* a1q = (const float*)&a11;
        #pragma unroll
        for (int i = 0; i < 4; i++) {
            {
                const float re = rep[i] * mult;
                const float sv = hpp[i] + re - tpp[i];
                const float nv = hnp[i] + re - tnp[i];
                const float A0 = a0p[i], A1 = a1p[i];
                aa   = fmaf(A0, A0, aa);
                ab   = fmaf(A0, A1, ab);
                dd   = fmaf(A1, A1, dd);
                as0p = fmaf(A0, sv, as0p);
                as1p = fmaf(A1, sv, as1p);
                ssp  = fmaf(sv, sv, ssp);
                as0n = fmaf(A0, nv, as0n);
                as1n = fmaf(A1, nv, as1n);
                ssn  = fmaf(nv, nv, ssn);
            }
            {
                const float re = req[i] * mult;
                const float sv = hpq[i] + re - tpq[i];
                const float nv = hnq[i] + re - tnq[i];
                const float A0 = a0q[i], A1 = a1q[i];
                aa   = fmaf(A0, A0, aa);
                ab   = fmaf(A0, A1, ab);
                dd   = fmaf(A1, A1, dd);
                as0p = fmaf(A0, sv, as0p);
                as1p = fmaf(A1, sv, as1p);
                ssp  = fmaf(sv, sv, ssp);
                as0n = fmaf(A0, nv, as0n);
                as1n = fmaf(A1, nv, as1n);
                ssn  = fmaf(nv, nv, ssn);
            }
        }
    }

    // Fused butterfly allreduce of 9 scalars
    #pragma unroll
    for (int m = 16; m > 0; m >>= 1) {
        aa   += __shfl_xor_sync(0xffffffffu, aa,   m);
        ab   += __shfl_xor_sync(0xffffffffu, ab,   m);
        dd   += __shfl_xor_sync(0xffffffffu, dd,   m);
        as0p += __shfl_xor_sync(0xffffffffu, as0p, m);
        as1p += __shfl_xor_sync(0xffffffffu, as1p, m);
        ssp  += __shfl_xor_sync(0xffffffffu, ssp,  m);
        as0n += __shfl_xor_sync(0xffffffffu, as0n, m);
        as1n += __shfl_xor_sync(0xffffffffu, as1n, m);
        ssn  += __shfl_xor_sync(0xffffffffu, ssn,  m);
    }

    if (lane == 0) {
        const float det = aa * dd - ab * ab;
        float scp, scn;
        if (det != 0.0f) {
            // exact normal-equation solve -> ||proj||^2 = ss - c . As
            const float inv_det = 1.0f / det;
            const float c0p = ( dd * as0p - ab * as1p) * inv_det;
            const float c1p = (-ab * as0p + aa * as1p) * inv_det;
            const float c0n = ( dd * as0n - ab * as1n) * inv_det;
            const float c1n = (-ab * as0n + aa * as1n) * inv_det;
            scp = ssp - c0p * as0p - c1p * as1p;
            scn = ssn - c0n * as0n - c1n * as1n;
        } else {
            // fallback c = As / aa is NOT the exact solution -> full quadratic
            const float inv_a = 1.0f / aa;
            const float c0p = as0p * inv_a, c1p = as1p * inv_a;
            const float c0n = as0n * inv_a, c1n = as1n * inv_a;
            scp = ssp - 2.0f * (c0p * as0p + c1p * as1p)
                + c0p * c0p * aa + 2.0f * c0p * c1p * ab + c1p * c1p * dd;
            scn = ssn - 2.0f * (c0n * as0n + c1n * as1n)
                + c0n * c0n * aa + 2.0f * c0n * c1n * ab + c1n * c1n * dd;
        }
        out[s]     = scp;
        out[B + s] = scn;
    }
}

extern "C" void kernel_launch(void* const* d_in, const int* in_sizes, int n_in,
                              void* d_out, int out_size) {
    const int*   pos_h    = (const int*)  d_in[0];
    const int*   pos_t    = (const int*)  d_in[1];
    const int*   pos_r    = (const int*)  d_in[2];
    const int*   neg_h    = (const int*)  d_in[3];
    const int*   neg_t    = (const int*)  d_in[4];
    // d_in[5] = neg_r (unused by the reference)
    const float* ent_emb  = (const float*)d_in[6];
    const float* heads    = (const float*)d_in[7];
    const float* bases    = (const float*)d_in[8];
    const int*   rel2head = (const int*)  d_in[9];
    const float* rel2mult = (const float*)d_in[10];
    float* out = (float*)d_out;

    const int B = in_sizes[0];
    const int blocks = (B + WARPS_PER_BLOCK - 1) / WARPS_PER_BLOCK;
    transint_kernel<<<blocks, WARPS_PER_BLOCK * 32>>>(
        pos_h, pos_t, pos_r, neg_h, neg_t,
        ent_emb, heads, bases, rel2head, rel2mult, out, B);
}